// round 16
// baseline (speedup 1.0000x reference)
#include <cuda_runtime.h>
#include <cstdint>

// out[b, g, k, c] = textures[b, group_idx[g, k], c]
// B=2, T=1e6, C=16 (fp32), G=500000, K=9.
//
// R15: resubmit of R14 (infra failure last round, no kernel verdict).
// Slab passes — restructure traffic instead of tuning rate.
// Single-pass floor established (R8-R13): 1.05GB @ ~6.4TB/s, reads ~460MB vs
// 128MB compulsory because reuse distance (random over 64MB) exceeds L2
// retention under write flow. Fix by construction: P=4 passes, pass p only
// gathers chunks whose texel falls in slab p (16MB). Live set per pass =
// 2 slabs + 18MB idx = ~50MB << 126MB L2 -> gathers hit after first touch.
// Pass is the slow grid.y index (x-major dispatch serializes passes, the
// same mechanism that batch-serializes since R3). Every chunk is stored in
// exactly one pass => each output written exactly once (poison rule holds).
// Skeleton = R8 best config: U=3, 6 CTAs/SM, LDG.256 evict_last, STG.256 cs.
// Slab filter folds into the existing ii<total32 guard (~2 extra regs).

#define U 3
#define NPASS 4

__device__ __forceinline__ void ldg256_evict_last(const float4* p, unsigned long long d[4]) {
    asm volatile("ld.global.nc.L2::evict_last.v4.b64 {%0,%1,%2,%3}, [%4];"
                 : "=l"(d[0]), "=l"(d[1]), "=l"(d[2]), "=l"(d[3])
                 : "l"(p));
}

__device__ __forceinline__ void stg256_cs(float4* p, const unsigned long long d[4]) {
    asm volatile("st.global.cs.v4.b64 [%0], {%1,%2,%3,%4};"
                 :: "l"(p), "l"(d[0]), "l"(d[1]), "l"(d[2]), "l"(d[3]) : "memory");
}

__global__ void __launch_bounds__(256, 6)
tmscnn_gather_kernel(const float4* __restrict__ tex,     // [B, T*C/4]
                     const int*    __restrict__ gidx,    // [G*K]
                     float4*       __restrict__ out,     // [B, G*K*4]
                     int total32,                        // G*K*2 (32B chunks)
                     int slabT,                          // texels per slab
                     int nbatch,                         // B
                     long long tex_batch_stride_f4,      // T*C/4
                     long long out_batch_stride_f4)      // G*K*4
{
    // grid.y = NPASS*B; pass is the SLOW index -> passes run sequentially.
    const int pass = blockIdx.y / nbatch;
    const int b    = blockIdx.y % nbatch;

    const int lo = pass * slabT;
    const int hi = lo + slabT;

    const int stride = gridDim.x * blockDim.x;
    const int i0 = blockIdx.x * blockDim.x + threadIdx.x;

    const float4* tex_b = tex + (long long)b * tex_batch_stride_f4;
    float4*       out_b = out + (long long)b * out_batch_stride_f4;

    int ii[U];
    int tt[U];
    unsigned long long vv[U][4];

    // Phase 1: index loads + slab filter (deactivate via the bounds guard)
    #pragma unroll
    for (int u = 0; u < U; u++) {
        ii[u] = i0 + u * stride;
        tt[u] = 0;
        if (ii[u] < total32) {
            int t = __ldg(gidx + (ii[u] >> 1));
            tt[u] = t;
            if (t < lo || t >= hi) ii[u] = total32;   // not my slab this pass
        }
    }

    // Phase 2: independent 32B gathers, LDG.256 with L2 evict_last
    #pragma unroll
    for (int u = 0; u < U; u++) {
        if (ii[u] < total32) {
            const float4* src = tex_b + (long long)tt[u] * 4 + (ii[u] & 1) * 2;
            ldg256_evict_last(src, vv[u]);
        }
    }

    // Phase 3: evict-first streaming stores, one STG.256 per chunk
    #pragma unroll
    for (int u = 0; u < U; u++) {
        if (ii[u] < total32)
            stg256_cs(out_b + (long long)ii[u] * 2, vv[u]);
    }
}

extern "C" void kernel_launch(void* const* d_in, const int* in_sizes, int n_in,
                              void* d_out, int out_size)
{
    // metadata order: mesh_ids [B] int32, textures [B,T,C] f32, group_idx [G,K] int32
    const float* textures = (const float*)d_in[1];
    const int*   gidx     = (const int*)d_in[2];
    float*       out      = (float*)d_out;

    int B  = in_sizes[0];             // 2
    int GK = in_sizes[2];             // G*K = 4,500,000
    long long TC = (long long)in_sizes[1] / B;   // T*C = 16,000,000

    int C = (int)((long long)out_size / ((long long)B * GK));  // 16
    int T = (int)(TC / C);                                     // 1,000,000

    int total32 = GK * 2;             // 9,000,000 32B chunks per batch
    long long tex_stride_f4 = TC / 4; // 4,000,000
    long long out_stride_f4 = (long long)GK * 4;

    int slabT = (T + NPASS - 1) / NPASS;   // 250,000 texels per slab

    int threads_needed = (total32 + U - 1) / U;
    int blocks_per_pass = (threads_needed + 255) / 256;

    dim3 block(256);
    dim3 grid(blocks_per_pass, NPASS * B);

    tmscnn_gather_kernel<<<grid, block>>>(
        (const float4*)textures, gidx, (float4*)out,
        total32, slabT, B, tex_stride_f4, out_stride_f4);
}

// round 17
// speedup vs baseline: 1.3197x; 1.3197x over previous
#include <cuda_runtime.h>
#include <cstdint>

// out[b, g, k, c] = textures[b, group_idx[g, k], c]
// B=2, T=1e6, C=16 (fp32), G=500000, K=9.
//
// R17: slab passes, MLP-corrected. R16 (NPASS=4, U=3) PROVED the traffic
// mechanism (847MB < 1050MB single-pass floor) but collapsed to 2.5TB/s:
// 25% activity -> 0.75 active gathers/thread -> 1.2KB/SM in flight, far
// below the 3.4-4.6KB/SM band needed for ~6.4TB/s. Fix:
//   NPASS=2: live set 2x32MB slabs + 18MB idx = 82MB < 126MB L2 (residency
//            kept), activity 50%, traversal overhead halved.
//   U=6 @ __launch_bounds__(256,4): ~3 active gathers/thread = ~96B ->
//            32 warps x 96B = 3KB/SM active in-flight, inside the band.
//   ii[u] recomputed per phase (not stored) to fit ~64 regs.
// Stores are 32B sector-aligned so sparsity costs no DRAM write
// amplification. Pass = slow grid.y index (x-major dispatch serializes).

#define U 6
#define NPASS 2

__device__ __forceinline__ void ldg256_evict_last(const float4* p, unsigned long long d[4]) {
    asm volatile("ld.global.nc.L2::evict_last.v4.b64 {%0,%1,%2,%3}, [%4];"
                 : "=l"(d[0]), "=l"(d[1]), "=l"(d[2]), "=l"(d[3])
                 : "l"(p));
}

__device__ __forceinline__ void stg256_cs(float4* p, const unsigned long long d[4]) {
    asm volatile("st.global.cs.v4.b64 [%0], {%1,%2,%3,%4};"
                 :: "l"(p), "l"(d[0]), "l"(d[1]), "l"(d[2]), "l"(d[3]) : "memory");
}

__global__ void __launch_bounds__(256, 4)
tmscnn_gather_kernel(const float4* __restrict__ tex,     // [B, T*C/4]
                     const int*    __restrict__ gidx,    // [G*K]
                     float4*       __restrict__ out,     // [B, G*K*4]
                     int total32,                        // G*K*2 (32B chunks)
                     int slabT,                          // texels per slab
                     int nbatch,                         // B
                     long long tex_batch_stride_f4,      // T*C/4
                     long long out_batch_stride_f4)      // G*K*4
{
    // grid.y = NPASS*B; pass is the SLOW index -> passes run sequentially.
    const int pass = blockIdx.y / nbatch;
    const int b    = blockIdx.y % nbatch;

    const int lo = pass * slabT;
    const int hi = lo + slabT;

    const int stride = gridDim.x * blockDim.x;
    const int i0 = blockIdx.x * blockDim.x + threadIdx.x;

    const float4* tex_b = tex + (long long)b * tex_batch_stride_f4;
    float4*       out_b = out + (long long)b * out_batch_stride_f4;

    // tt[u] == -1 encodes "inactive this pass"; ii recomputed per phase.
    int tt[U];
    unsigned long long vv[U][4];

    // Phase 1: index loads + slab filter
    #pragma unroll
    for (int u = 0; u < U; u++) {
        int i = i0 + u * stride;
        tt[u] = -1;
        if (i < total32) {
            int t = __ldg(gidx + (i >> 1));
            if (t >= lo && t < hi) tt[u] = t;
        }
    }

    // Phase 2: independent 32B gathers, LDG.256 with L2 evict_last
    #pragma unroll
    for (int u = 0; u < U; u++) {
        if (tt[u] >= 0) {
            int i = i0 + u * stride;
            const float4* src = tex_b + (long long)tt[u] * 4 + (i & 1) * 2;
            ldg256_evict_last(src, vv[u]);
        }
    }

    // Phase 3: evict-first streaming stores (32B sector-aligned)
    #pragma unroll
    for (int u = 0; u < U; u++) {
        if (tt[u] >= 0) {
            int i = i0 + u * stride;
            stg256_cs(out_b + (long long)i * 2, vv[u]);
        }
    }
}

extern "C" void kernel_launch(void* const* d_in, const int* in_sizes, int n_in,
                              void* d_out, int out_size)
{
    // metadata order: mesh_ids [B] int32, textures [B,T,C] f32, group_idx [G,K] int32
    const float* textures = (const float*)d_in[1];
    const int*   gidx     = (const int*)d_in[2];
    float*       out      = (float*)d_out;

    int B  = in_sizes[0];             // 2
    int GK = in_sizes[2];             // G*K = 4,500,000
    long long TC = (long long)in_sizes[1] / B;   // T*C = 16,000,000

    int C = (int)((long long)out_size / ((long long)B * GK));  // 16
    int T = (int)(TC / C);                                     // 1,000,000

    int total32 = GK * 2;             // 9,000,000 32B chunks per batch
    long long tex_stride_f4 = TC / 4; // 4,000,000
    long long out_stride_f4 = (long long)GK * 4;

    int slabT = (T + NPASS - 1) / NPASS;   // 500,000 texels per slab

    int threads_needed = (total32 + U - 1) / U;
    int blocks_per_pass = (threads_needed + 255) / 256;

    dim3 block(256);
    dim3 grid(blocks_per_pass, NPASS * B);

    tmscnn_gather_kernel<<<grid, block>>>(
        (const float4*)textures, gidx, (float4*)out,
        total32, slabT, B, tex_stride_f4, out_stride_f4);
}